// round 1
// baseline (speedup 1.0000x reference)
#include <cuda_runtime.h>
#include <cstdint>

#define NUM_LEVELS 16
#define LOG2_HASHMAP 19
#define TABLE_SIZE (1u << LOG2_HASHMAP)
#define HASH_MASK (TABLE_SIZE - 1u)
#define N_QUERIES (1 << 20)

// primes: dim0 * 1, dim1 * 2654435761, dim2 * 805459861
#define P1 2654435761u
#define P2 805459861u

__global__ void __launch_bounds__(256)
grid_encode_kernel(const float* __restrict__ inp,
                   const float* __restrict__ emb,
                   const int* __restrict__ bound_ptr,
                   float* __restrict__ out)
{
    int tid = blockIdx.x * blockDim.x + threadIdx.x;
    if (tid >= N_QUERIES * NUM_LEVELS) return;
    int q = tid >> 4;
    int l = tid & 15;

    float inv_b = 1.0f / (float)(*bound_ptr);

    // channel permutation [2, 0, 1]
    float x0 = inp[3 * q + 2];
    float x1 = inp[3 * q + 0];
    float x2 = inp[3 * q + 1];

    float u0 = (x0 * inv_b + 1.0f) * 0.5f;
    float u1 = (x1 * inv_b + 1.0f) * 0.5f;
    float u2 = (x2 * inv_b + 1.0f) * 0.5f;

    float res = (float)(16u << l);   // floor(16 * 2^l), exact

    float p0 = u0 * res - 0.5f;
    float p1 = u1 * res - 0.5f;
    float p2 = u2 * res - 0.5f;

    float f0 = floorf(p0), f1 = floorf(p1), f2 = floorf(p2);
    float fr0 = p0 - f0, fr1 = p1 - f1, fr2 = p2 - f2;

    int c0 = (int)f0, c1 = (int)f1, c2 = (int)f2;

    // precompute hashed components for both corner positions per dim
    uint32_t h0a = (uint32_t)c0;            // * 1
    uint32_t h0b = (uint32_t)(c0 + 1);
    uint32_t h1a = (uint32_t)c1 * P1;
    uint32_t h1b = (uint32_t)(c1 + 1) * P1;
    uint32_t h2a = (uint32_t)c2 * P2;
    uint32_t h2b = (uint32_t)(c2 + 1) * P2;

    const float2* table = (const float2*)(emb) + (size_t)l * TABLE_SIZE;

    uint32_t idx[8];
    idx[0] = (h0a ^ h1a ^ h2a) & HASH_MASK;
    idx[1] = (h0a ^ h1a ^ h2b) & HASH_MASK;
    idx[2] = (h0a ^ h1b ^ h2a) & HASH_MASK;
    idx[3] = (h0a ^ h1b ^ h2b) & HASH_MASK;
    idx[4] = (h0b ^ h1a ^ h2a) & HASH_MASK;
    idx[5] = (h0b ^ h1a ^ h2b) & HASH_MASK;
    idx[6] = (h0b ^ h1b ^ h2a) & HASH_MASK;
    idx[7] = (h0b ^ h1b ^ h2b) & HASH_MASK;

    // issue all 8 gathers back-to-back for MLP
    float2 v0 = __ldg(&table[idx[0]]);
    float2 v1 = __ldg(&table[idx[1]]);
    float2 v2 = __ldg(&table[idx[2]]);
    float2 v3 = __ldg(&table[idx[3]]);
    float2 v4 = __ldg(&table[idx[4]]);
    float2 v5 = __ldg(&table[idx[5]]);
    float2 v6 = __ldg(&table[idx[6]]);
    float2 v7 = __ldg(&table[idx[7]]);

    float w0a = 1.0f - fr0, w0b = fr0;
    float w1a = 1.0f - fr1, w1b = fr1;
    float w2a = 1.0f - fr2, w2b = fr2;

    float waa = w0a * w1a, wab = w0a * w1b;
    float wba = w0b * w1a, wbb = w0b * w1b;

    float w[8];
    w[0] = waa * w2a;  w[1] = waa * w2b;
    w[2] = wab * w2a;  w[3] = wab * w2b;
    w[4] = wba * w2a;  w[5] = wba * w2b;
    w[6] = wbb * w2a;  w[7] = wbb * w2b;

    float ox = 0.0f, oy = 0.0f;
    ox = fmaf(w[0], v0.x, ox); oy = fmaf(w[0], v0.y, oy);
    ox = fmaf(w[1], v1.x, ox); oy = fmaf(w[1], v1.y, oy);
    ox = fmaf(w[2], v2.x, ox); oy = fmaf(w[2], v2.y, oy);
    ox = fmaf(w[3], v3.x, ox); oy = fmaf(w[3], v3.y, oy);
    ox = fmaf(w[4], v4.x, ox); oy = fmaf(w[4], v4.y, oy);
    ox = fmaf(w[5], v5.x, ox); oy = fmaf(w[5], v5.y, oy);
    ox = fmaf(w[6], v6.x, ox); oy = fmaf(w[6], v6.y, oy);
    ox = fmaf(w[7], v7.x, ox); oy = fmaf(w[7], v7.y, oy);

    // out[q][2l .. 2l+1]; byte offset is 8-aligned (2l even)
    float2* o = (float2*)(out + (size_t)q * (NUM_LEVELS * 2)) + l;
    *o = make_float2(ox, oy);
}

extern "C" void kernel_launch(void* const* d_in, const int* in_sizes, int n_in,
                              void* d_out, int out_size)
{
    const float* inp   = (const float*)d_in[0];
    const float* emb   = (const float*)d_in[1];
    const int*   bound = (const int*)d_in[2];
    float* out = (float*)d_out;

    int total = N_QUERIES * NUM_LEVELS;
    int block = 256;
    int grid = (total + block - 1) / block;
    grid_encode_kernel<<<grid, block>>>(inp, emb, bound, out);
}

// round 2
// speedup vs baseline: 1.2306x; 1.2306x over previous
#include <cuda_runtime.h>
#include <cstdint>

#define NUM_LEVELS 16
#define LOG2_HASHMAP 19
#define TABLE_SIZE (1u << LOG2_HASHMAP)
#define HASH_MASK (TABLE_SIZE - 1u)
#define N_QUERIES (1 << 20)

#define P1 2654435761u
#define P2 805459861u

__global__ void __launch_bounds__(256)
grid_encode_kernel(const float* __restrict__ inp,
                   const float* __restrict__ emb,
                   const int* __restrict__ bound_ptr,
                   float* __restrict__ out)
{
    int tid = blockIdx.x * blockDim.x + threadIdx.x;
    if (tid >= N_QUERIES * NUM_LEVELS) return;
    int q = tid >> 4;
    int l = tid & 15;

    float inv_b = 1.0f / (float)(*bound_ptr);

    // channel permutation [2, 0, 1]
    float x0 = inp[3 * q + 2];
    float x1 = inp[3 * q + 0];
    float x2 = inp[3 * q + 1];

    float u0 = (x0 * inv_b + 1.0f) * 0.5f;
    float u1 = (x1 * inv_b + 1.0f) * 0.5f;
    float u2 = (x2 * inv_b + 1.0f) * 0.5f;

    float res = (float)(16u << l);   // floor(16 * 2^l), exact

    float p0 = u0 * res - 0.5f;
    float p1 = u1 * res - 0.5f;
    float p2 = u2 * res - 0.5f;

    float f0 = floorf(p0), f1 = floorf(p1), f2 = floorf(p2);
    float fr0 = p0 - f0, fr1 = p1 - f1, fr2 = p2 - f2;

    int c0 = (int)f0, c1 = (int)f1, c2 = (int)f2;

    // hashed components (dim0 prime is 1)
    uint32_t hc0  = (uint32_t)c0;
    uint32_t hc0b = (uint32_t)(c0 + 1);
    uint32_t h1a = (uint32_t)c1 * P1;
    uint32_t h1b = (uint32_t)(c1 + 1) * P1;
    uint32_t h2a = (uint32_t)c2 * P2;
    uint32_t h2b = (uint32_t)(c2 + 1) * P2;

    const float2* table = (const float2*)(emb) + (size_t)l * TABLE_SIZE;

    // 4 combos over (dim1, dim2): t bit1 = dim1 offset, bit0 = dim2 offset
    uint32_t hjk0 = h1a ^ h2a;
    uint32_t hjk1 = h1a ^ h2b;
    uint32_t hjk2 = h1b ^ h2a;
    uint32_t hjk3 = h1b ^ h2b;

    // z = index of corner with dim0 = c0. Its aligned float4 partner is z^1.
    uint32_t z0 = (hjk0 ^ hc0) & HASH_MASK;
    uint32_t z1 = (hjk1 ^ hc0) & HASH_MASK;
    uint32_t z2 = (hjk2 ^ hc0) & HASH_MASK;
    uint32_t z3 = (hjk3 ^ hc0) & HASH_MASK;

    bool even = ((c0 & 1) == 0);   // if even: partner z^1 == corner at c0+1

    // Always load the aligned pair containing z (covers z and z^1).
    float4 a0 = __ldg((const float4*)(table + (z0 & ~1u)));
    float4 a1 = __ldg((const float4*)(table + (z1 & ~1u)));
    float4 a2 = __ldg((const float4*)(table + (z2 & ~1u)));
    float4 a3 = __ldg((const float4*)(table + (z3 & ~1u)));

    // For odd c0, fetch the c0+1 corners separately (predicated).
    float2 b0, b1, b2, b3;
    if (!even) {
        uint32_t y0 = (hjk0 ^ hc0b) & HASH_MASK;
        uint32_t y1 = (hjk1 ^ hc0b) & HASH_MASK;
        uint32_t y2 = (hjk2 ^ hc0b) & HASH_MASK;
        uint32_t y3 = (hjk3 ^ hc0b) & HASH_MASK;
        b0 = __ldg(table + y0);
        b1 = __ldg(table + y1);
        b2 = __ldg(table + y2);
        b3 = __ldg(table + y3);
    }

    // Extract entry z (lo/hi half by z&1) and its partner from each float4.
    float2 e0_0 = (z0 & 1) ? make_float2(a0.z, a0.w) : make_float2(a0.x, a0.y);
    float2 e0_1 = (z1 & 1) ? make_float2(a1.z, a1.w) : make_float2(a1.x, a1.y);
    float2 e0_2 = (z2 & 1) ? make_float2(a2.z, a2.w) : make_float2(a2.x, a2.y);
    float2 e0_3 = (z3 & 1) ? make_float2(a3.z, a3.w) : make_float2(a3.x, a3.y);

    float2 p0_0 = (z0 & 1) ? make_float2(a0.x, a0.y) : make_float2(a0.z, a0.w);
    float2 p0_1 = (z1 & 1) ? make_float2(a1.x, a1.y) : make_float2(a1.z, a1.w);
    float2 p0_2 = (z2 & 1) ? make_float2(a2.x, a2.y) : make_float2(a2.z, a2.w);
    float2 p0_3 = (z3 & 1) ? make_float2(a3.x, a3.y) : make_float2(a3.z, a3.w);

    // corner at dim0 = c0+1: partner from the float4 if even, else the extra load
    float2 e1_0 = even ? p0_0 : b0;
    float2 e1_1 = even ? p0_1 : b1;
    float2 e1_2 = even ? p0_2 : b2;
    float2 e1_3 = even ? p0_3 : b3;

    float w0a = 1.0f - fr0, w0b = fr0;
    float w1a = 1.0f - fr1, w1b = fr1;
    float w2a = 1.0f - fr2, w2b = fr2;

    // combo weights over (dim1, dim2)
    float wc0 = w1a * w2a;
    float wc1 = w1a * w2b;
    float wc2 = w1b * w2a;
    float wc3 = w1b * w2b;

    // blend dim0 first, then accumulate per combo
    float ox = 0.0f, oy = 0.0f;
    ox = fmaf(wc0, fmaf(w0a, e0_0.x, w0b * e1_0.x), ox);
    oy = fmaf(wc0, fmaf(w0a, e0_0.y, w0b * e1_0.y), oy);
    ox = fmaf(wc1, fmaf(w0a, e0_1.x, w0b * e1_1.x), ox);
    oy = fmaf(wc1, fmaf(w0a, e0_1.y, w0b * e1_1.y), oy);
    ox = fmaf(wc2, fmaf(w0a, e0_2.x, w0b * e1_2.x), ox);
    oy = fmaf(wc2, fmaf(w0a, e0_2.y, w0b * e1_2.y), oy);
    ox = fmaf(wc3, fmaf(w0a, e0_3.x, w0b * e1_3.x), ox);
    oy = fmaf(wc3, fmaf(w0a, e0_3.y, w0b * e1_3.y), oy);

    float2* o = (float2*)(out + (size_t)q * (NUM_LEVELS * 2)) + l;
    *o = make_float2(ox, oy);
}

extern "C" void kernel_launch(void* const* d_in, const int* in_sizes, int n_in,
                              void* d_out, int out_size)
{
    const float* inp   = (const float*)d_in[0];
    const float* emb   = (const float*)d_in[1];
    const int*   bound = (const int*)d_in[2];
    float* out = (float*)d_out;

    int total = N_QUERIES * NUM_LEVELS;
    int block = 256;
    int grid = (total + block - 1) / block;
    grid_encode_kernel<<<grid, block>>>(inp, emb, bound, out);
}

// round 3
// speedup vs baseline: 1.4015x; 1.1389x over previous
#include <cuda_runtime.h>
#include <cuda_fp16.h>
#include <cstdint>

#define NUM_LEVELS 16
#define LOG2_HASHMAP 19
#define TABLE_SIZE (1u << LOG2_HASHMAP)
#define HASH_MASK (TABLE_SIZE - 1u)
#define N_QUERIES (1 << 20)

#define P1 2654435761u
#define P2 805459861u

// fp16-repacked table: entry i of level l at g_tab[l*TABLE_SIZE + i], 4 bytes each.
__device__ uint32_t g_tab[NUM_LEVELS * TABLE_SIZE];

__global__ void __launch_bounds__(256)
convert_kernel(const float4* __restrict__ emb)
{
    int i = blockIdx.x * blockDim.x + threadIdx.x;   // 2 entries per thread
    float4 e = emb[i];
    __half2 a = __floats2half2_rn(e.x, e.y);
    __half2 b = __floats2half2_rn(e.z, e.w);
    uint2 pk;
    pk.x = *reinterpret_cast<uint32_t*>(&a);
    pk.y = *reinterpret_cast<uint32_t*>(&b);
    reinterpret_cast<uint2*>(g_tab)[i] = pk;
}

__device__ __forceinline__ float2 h2f(uint32_t u)
{
    __half2 h = *reinterpret_cast<__half2*>(&u);
    return __half22float2(h);
}

__device__ __forceinline__ uint32_t sel4(uint4 q, uint32_t s)
{
    uint32_t lo = (s & 1) ? q.y : q.x;
    uint32_t hi = (s & 1) ? q.w : q.z;
    return (s & 2) ? hi : lo;
}

__global__ void __launch_bounds__(256)
grid_encode_kernel(const float* __restrict__ inp,
                   const int* __restrict__ bound_ptr,
                   float* __restrict__ out)
{
    int tid = blockIdx.x * blockDim.x + threadIdx.x;
    if (tid >= N_QUERIES * NUM_LEVELS) return;
    int q = tid >> 4;
    int l = tid & 15;

    float inv_b = 1.0f / (float)(*bound_ptr);

    // channel permutation [2, 0, 1]
    float x0 = inp[3 * q + 2];
    float x1 = inp[3 * q + 0];
    float x2 = inp[3 * q + 1];

    float u0 = (x0 * inv_b + 1.0f) * 0.5f;
    float u1 = (x1 * inv_b + 1.0f) * 0.5f;
    float u2 = (x2 * inv_b + 1.0f) * 0.5f;

    float res = (float)(16u << l);

    float p0 = u0 * res - 0.5f;
    float p1 = u1 * res - 0.5f;
    float p2 = u2 * res - 0.5f;

    float f0 = floorf(p0), f1 = floorf(p1), f2 = floorf(p2);
    float fr0 = p0 - f0, fr1 = p1 - f1, fr2 = p2 - f2;

    int c0 = (int)f0, c1 = (int)f1, c2 = (int)f2;

    uint32_t hc0  = (uint32_t)c0;
    uint32_t hc0b = (uint32_t)(c0 + 1);
    uint32_t h1a = (uint32_t)c1 * P1;
    uint32_t h1b = (uint32_t)(c1 + 1) * P1;
    uint32_t h2a = (uint32_t)c2 * P2;
    uint32_t h2b = (uint32_t)(c2 + 1) * P2;

    uint32_t hjk0 = h1a ^ h2a;
    uint32_t hjk1 = h1a ^ h2b;
    uint32_t hjk2 = h1b ^ h2a;
    uint32_t hjk3 = h1b ^ h2b;

    // corner (dim0 = c0) indices; corner (dim0 = c0+1) is z ^ (c0^(c0+1))
    uint32_t z0 = (hjk0 ^ hc0) & HASH_MASK;
    uint32_t z1 = (hjk1 ^ hc0) & HASH_MASK;
    uint32_t z2 = (hjk2 ^ hc0) & HASH_MASK;
    uint32_t z3 = (hjk3 ^ hc0) & HASH_MASK;

    const uint32_t* tab = g_tab + (size_t)l * TABLE_SIZE;

    float w0a = 1.0f - fr0, w0b = fr0;
    float w1a = 1.0f - fr1, w1b = fr1;
    float w2a = 1.0f - fr2, w2b = fr2;

    float wc0 = w1a * w2a;
    float wc1 = w1a * w2b;
    float wc2 = w1b * w2a;
    float wc3 = w1b * w2b;

    float ox = 0.0f, oy = 0.0f;

#define ACC(U0, U1, WC)                                            \
    {                                                              \
        float2 ea_ = h2f(U0);                                      \
        float2 eb_ = h2f(U1);                                      \
        ox = fmaf(WC, fmaf(w0a, ea_.x, w0b * eb_.x), ox);          \
        oy = fmaf(WC, fmaf(w0a, ea_.y, w0b * eb_.y), oy);          \
    }

    uint32_t par = (uint32_t)c0 & 3u;

    if ((par & 1u) == 0u) {
        // c0 even: z^y == 1 -> one 8B aligned pair per combo
        uint2 A0 = __ldg((const uint2*)(tab + (z0 & ~1u)));
        uint2 A1 = __ldg((const uint2*)(tab + (z1 & ~1u)));
        uint2 A2 = __ldg((const uint2*)(tab + (z2 & ~1u)));
        uint2 A3 = __ldg((const uint2*)(tab + (z3 & ~1u)));
        ACC((z0 & 1) ? A0.y : A0.x, (z0 & 1) ? A0.x : A0.y, wc0);
        ACC((z1 & 1) ? A1.y : A1.x, (z1 & 1) ? A1.x : A1.y, wc1);
        ACC((z2 & 1) ? A2.y : A2.x, (z2 & 1) ? A2.x : A2.y, wc2);
        ACC((z3 & 1) ? A3.y : A3.x, (z3 & 1) ? A3.x : A3.y, wc3);
    } else if (par == 1u) {
        // c0 == 1 mod 4: z^y == 3 -> one 16B aligned quad per combo
        uint4 Q0 = __ldg((const uint4*)(tab + (z0 & ~3u)));
        uint4 Q1 = __ldg((const uint4*)(tab + (z1 & ~3u)));
        uint4 Q2 = __ldg((const uint4*)(tab + (z2 & ~3u)));
        uint4 Q3 = __ldg((const uint4*)(tab + (z3 & ~3u)));
        ACC(sel4(Q0, z0 & 3u), sel4(Q0, (z0 & 3u) ^ 3u), wc0);
        ACC(sel4(Q1, z1 & 3u), sel4(Q1, (z1 & 3u) ^ 3u), wc1);
        ACC(sel4(Q2, z2 & 3u), sel4(Q2, (z2 & 3u) ^ 3u), wc2);
        ACC(sel4(Q3, z3 & 3u), sel4(Q3, (z3 & 3u) ^ 3u), wc3);
    } else {
        // c0 == 3 mod 4: unmergeable -> two 4B loads per combo
        uint32_t y0 = (hjk0 ^ hc0b) & HASH_MASK;
        uint32_t y1 = (hjk1 ^ hc0b) & HASH_MASK;
        uint32_t y2 = (hjk2 ^ hc0b) & HASH_MASK;
        uint32_t y3 = (hjk3 ^ hc0b) & HASH_MASK;
        uint32_t a0 = __ldg(tab + z0);
        uint32_t a1 = __ldg(tab + z1);
        uint32_t a2 = __ldg(tab + z2);
        uint32_t a3 = __ldg(tab + z3);
        uint32_t b0 = __ldg(tab + y0);
        uint32_t b1 = __ldg(tab + y1);
        uint32_t b2 = __ldg(tab + y2);
        uint32_t b3 = __ldg(tab + y3);
        ACC(a0, b0, wc0);
        ACC(a1, b1, wc1);
        ACC(a2, b2, wc2);
        ACC(a3, b3, wc3);
    }
#undef ACC

    float2* o = (float2*)(out + (size_t)q * (NUM_LEVELS * 2)) + l;
    *o = make_float2(ox, oy);
}

extern "C" void kernel_launch(void* const* d_in, const int* in_sizes, int n_in,
                              void* d_out, int out_size)
{
    const float* inp   = (const float*)d_in[0];
    const float* emb   = (const float*)d_in[1];
    const int*   bound = (const int*)d_in[2];
    float* out = (float*)d_out;

    // Prepass: repack fp32 table -> fp16 (2 entries per thread)
    int conv_threads = (NUM_LEVELS * TABLE_SIZE) / 2;   // 8M
    convert_kernel<<<conv_threads / 256, 256>>>((const float4*)emb);

    int total = N_QUERIES * NUM_LEVELS;
    grid_encode_kernel<<<(total + 255) / 256, 256>>>(inp, bound, out);
}